// round 7
// baseline (speedup 1.0000x reference)
#include <cuda_runtime.h>
#include <cuda_fp16.h>
#include <math.h>

#define NN 50000
#define NPAD 50048
#define EE 600000
#define GG 512
#define HH 128
#define OUTD 256
#define LL 7
#define BNEPS 1e-5f
#define NB 49   // scan blocks of 1024

// ---------------- scratch (device globals; no allocs) ----------------
__device__ float  d_h[NPAD * HH];     // fp32 h (residual + pooling path) -- STREAMED (.cs)
__device__ __half d_hf[NPAD * HH];    // fp16 copy of h (gather path)     -- L2-HOT
__device__ uint2  d_Apk[NPAD * 64];   // packed A fragments               -- STREAMED (.cs)
__device__ float  d_A4[NN * 4];
__device__ int    d_degI[NN];
__device__ int    d_rowstart[NN + 1];
__device__ int    d_cursor[NN];
__device__ int    d_csrc[EE];         // L2-HOT
__device__ float  d_Se[NN * 2];
__device__ float  d_Shat[NPAD * 3];
__device__ float  d_dinv[NN];
__device__ int    d_bsum[NB];
__device__ uint4  d_Wpk[LL * 4096];
__device__ float  d_Wc0[4 * HH];
__device__ float  d_Wec[8 * 3 * HH];
__device__ float  d_bc[8 * HH];

static __device__ __forceinline__ unsigned packh2(__half a, __half b) {
    __half2 h = __halves2half2(a, b);
    return *(unsigned*)&h;
}

static __device__ __forceinline__ unsigned packhilo(float x, float y, unsigned& lo) {
    __half hx = __float2half_rn(x), hy = __float2half_rn(y);
    __half lx = __float2half_rn(x - __half2float(hx));
    __half ly = __float2half_rn(y - __half2float(hy));
    lo = packh2(lx, ly);
    return packh2(hx, hy);
}

static __device__ __forceinline__ void mma16816(float* c,
        unsigned a0, unsigned a1, unsigned a2, unsigned a3,
        unsigned b0, unsigned b1) {
    asm volatile(
        "mma.sync.aligned.m16n8k16.row.col.f32.f16.f16.f32 "
        "{%0,%1,%2,%3}, {%4,%5,%6,%7}, {%8,%9}, {%0,%1,%2,%3};\n"
        : "+f"(c[0]), "+f"(c[1]), "+f"(c[2]), "+f"(c[3])
        : "r"(a0), "r"(a1), "r"(a2), "r"(a3), "r"(b0), "r"(b1));
}

// ---------------- graph preprocessing ----------------
__global__ void k_zero() {
    int i = blockIdx.x * blockDim.x + threadIdx.x;
    if (i < NN) { d_degI[i] = 0; d_cursor[i] = 0; }
    if (i < 2 * NN) d_Se[i] = 0.f;
}

__global__ void k_deg_se(const int* __restrict__ dst, const float* __restrict__ ea) {
    int e = blockIdx.x * blockDim.x + threadIdx.x;
    if (e >= EE) return;
    int d = dst[e];
    atomicAdd(&d_degI[d], 1);
    atomicAdd(&d_Se[d * 2 + 0], ea[e * 2 + 0]);
    atomicAdd(&d_Se[d * 2 + 1], ea[e * 2 + 1]);
}

__global__ void k_bsum() {
    __shared__ int sred[8];
    int b = blockIdx.x, t = threadIdx.x;
    int base = b * 1024 + t * 4;
    int s = 0;
    #pragma unroll
    for (int i = 0; i < 4; i++) { int idx = base + i; s += (idx < NN) ? d_degI[idx] : 0; }
    for (int o = 16; o > 0; o >>= 1) s += __shfl_down_sync(~0u, s, o);
    if ((t & 31) == 0) sred[t >> 5] = s;
    __syncthreads();
    if (t == 0) { int tot = 0; for (int w = 0; w < 8; w++) tot += sred[w]; d_bsum[b] = tot; }
}

__global__ void k_rowstart_shat() {
    __shared__ int sb[NB];
    __shared__ int wsum[8];
    int b = blockIdx.x, t = threadIdx.x;
    if (t < NB) sb[t] = d_bsum[t];
    int base_idx = b * 1024 + t * 4;
    int v[4];
    #pragma unroll
    for (int i = 0; i < 4; i++) { int idx = base_idx + i; v[i] = (idx < NN) ? d_degI[idx] : 0; }
    int tsum = v[0] + v[1] + v[2] + v[3];
    int lane = t & 31, wid = t >> 5;
    int s = tsum;
    for (int o = 1; o < 32; o <<= 1) { int u = __shfl_up_sync(~0u, s, o); if (lane >= o) s += u; }
    if (lane == 31) wsum[wid] = s;
    __syncthreads();
    if (t == 0) { int c = 0; for (int w = 0; w < 8; w++) { int x = wsum[w]; wsum[w] = c; c += x; } }
    __syncthreads();
    int base = 0;
    for (int i = 0; i < b; i++) base += sb[i];
    int run = s - tsum + wsum[wid] + base;
    #pragma unroll
    for (int i = 0; i < 4; i++) {
        int idx = base_idx + i;
        if (idx < NN) {
            d_rowstart[idx] = run;
            int dg = v[i];
            float inv = 1.0f / (float)max(dg, 1);
            d_dinv[idx] = inv;
            d_Shat[idx * 3 + 0] = d_Se[idx * 2 + 0] * inv;
            d_Shat[idx * 3 + 1] = d_Se[idx * 2 + 1] * inv;
            d_Shat[idx * 3 + 2] = (dg > 0) ? 1.0f : 0.0f;
        }
        run += v[i];
    }
    if (b == 0 && t == 0) d_rowstart[NN] = EE;
}

__global__ void k_fill(const int* __restrict__ src, const int* __restrict__ dst) {
    int e = blockIdx.x * blockDim.x + threadIdx.x;
    if (e >= EE) return;
    int d = dst[e];
    int pos = d_rowstart[d] + atomicAdd(&d_cursor[d], 1);
    d_csrc[pos] = src[e];
}

// ---------------- all weight folding in one kernel ----------------
__global__ void k_prep(
    const float* __restrict__ We0, const float* __restrict__ Wn0,
    const float* __restrict__ g0,  const float* __restrict__ v0,
    const float* __restrict__ be0, const float* __restrict__ bno0,
    const float* __restrict__ m0,  const float* __restrict__ bt0,
    const float* __restrict__ We_s, const float* __restrict__ Wn_s,
    const float* __restrict__ g_s,  const float* __restrict__ v_s,
    const float* __restrict__ be_s, const float* __restrict__ bno_s,
    const float* __restrict__ m_s,  const float* __restrict__ bt_s) {
    int idx = blockIdx.x * blockDim.x + threadIdx.x;
    if (idx < LL * 4096) {
        int l = idx / 4096, e = idx % 4096;
        int ks = e / 512;
        int rem = e % 512;
        int nf = rem / 32, lane = rem % 32;
        int g = lane >> 2, tig = lane & 3;
        int n = nf * 8 + g;
        int k0 = ks * 16 + tig * 2;
        const float* We = We_s + l * (HH + 2) * HH;
        const float* Wn = Wn_s + l * HH * HH;
        float s = g_s[l * HH + n] * rsqrtf(v_s[l * HH + n] + BNEPS);
        float w00 = 0.f, w01 = 0.f, w10 = 0.f, w11 = 0.f;
        #pragma unroll 4
        for (int m = 0; m < HH; m++) {
            float wn = Wn[m * HH + n];
            w00 += We[(k0 + 0) * HH + m] * wn;
            w01 += We[(k0 + 1) * HH + m] * wn;
            w10 += We[(k0 + 8) * HH + m] * wn;
            w11 += We[(k0 + 9) * HH + m] * wn;
        }
        w00 *= s; w01 *= s; w10 *= s; w11 *= s;
        uint4 o;
        o.x = packhilo(w00, w01, o.z);
        o.y = packhilo(w10, w11, o.w);
        d_Wpk[idx] = o;
        return;
    }
    int q = idx - LL * 4096;
    if (q < 4 * HH) {
        int k = q / HH, j = q % HH;
        float s = g0[j] * rsqrtf(v0[j] + BNEPS);
        float acc = 0.f;
        for (int m = 0; m < HH; m++) acc += We0[k * HH + m] * Wn0[m * HH + j];
        d_Wc0[q] = acc * s;
    } else if (q < 4 * HH + 8 * 3 * HH) {
        int t = q - 4 * HH;
        int l = t / (3 * HH);
        int r = (t / HH) % 3;
        int j = t % HH;
        const float* Wn; const float* row; float s;
        if (l == 0) {
            Wn = Wn0;
            s = g0[j] * rsqrtf(v0[j] + BNEPS);
            row = (r < 2) ? (We0 + (4 + r) * HH) : be0;
        } else {
            int lw = l - 1;
            Wn = Wn_s + lw * HH * HH;
            s = g_s[lw * HH + j] * rsqrtf(v_s[lw * HH + j] + BNEPS);
            row = (r < 2) ? (We_s + lw * (HH + 2) * HH + (HH + r) * HH) : (be_s + lw * HH);
        }
        float acc = 0.f;
        for (int m = 0; m < HH; m++) acc += row[m] * Wn[m * HH + j];
        d_Wec[l * 3 * HH + r * HH + j] = acc * s;
    } else if (q < 4 * HH + 8 * 3 * HH + 8 * HH) {
        int t = q - 4 * HH - 8 * 3 * HH;
        int l = t / HH, j = t % HH;
        float s, bn, mm, bt;
        if (l == 0) { s = g0[j] * rsqrtf(v0[j] + BNEPS); bn = bno0[j]; mm = m0[j]; bt = bt0[j]; }
        else {
            int lw = l - 1;
            s = g_s[lw * HH + j] * rsqrtf(v_s[lw * HH + j] + BNEPS);
            bn = bno_s[lw * HH + j]; mm = m_s[lw * HH + j]; bt = bt_s[lw * HH + j];
        }
        d_bc[l * HH + j] = (bn - mm) * s + bt;
    }
}

// ---------------- layer 0 ----------------
__global__ void k_agg4(const float* __restrict__ x) {
    int n = blockIdx.x * blockDim.x + threadIdx.x;
    if (n >= NN) return;
    int s0 = d_rowstart[n], s1 = d_rowstart[n + 1];
    float4 acc = make_float4(0.f, 0.f, 0.f, 0.f);
    const float4* x4 = (const float4*)x;
    for (int e = s0; e < s1; e++) {
        int s = d_csrc[e];
        float4 xv = x4[s];
        acc.x += xv.x; acc.y += xv.y; acc.z += xv.z; acc.w += xv.w;
    }
    float inv = d_dinv[n];
    ((float4*)d_A4)[n] = make_float4(acc.x * inv, acc.y * inv, acc.z * inv, acc.w * inv);
}

__global__ void k_update0(const float* __restrict__ x,
                          const float* __restrict__ Wr0, const float* __restrict__ br0) {
    int n = blockIdx.x * blockDim.x + threadIdx.x;
    int node = n >> 7;
    int j = n & 127;
    if (node >= NN) return;
    float4 a4 = ((const float4*)d_A4)[node];
    float4 xr = ((const float4*)x)[node];
    float s0 = d_Shat[node * 3 + 0], s1 = d_Shat[node * 3 + 1], s2 = d_Shat[node * 3 + 2];
    float v = d_bc[j];
    v += a4.x * d_Wc0[0 * HH + j] + a4.y * d_Wc0[1 * HH + j]
       + a4.z * d_Wc0[2 * HH + j] + a4.w * d_Wc0[3 * HH + j];
    v += s0 * d_Wec[0 * HH + j] + s1 * d_Wec[1 * HH + j] + s2 * d_Wec[2 * HH + j];
    float res = br0[j];
    res += xr.x * Wr0[0 * HH + j] + xr.y * Wr0[1 * HH + j]
         + xr.z * Wr0[2 * HH + j] + xr.w * Wr0[3 * HH + j];
    float out = fmaxf(v + res, 0.f);
    __stcs(&d_h[node * HH + j], out);
    d_hf[node * HH + j] = __float2half_rn(out);
}

// ---------------- layers 1..7 ----------------
// half-warp per node, gather from L2-hot fp16 copy; streaming output (.cs)
__global__ __launch_bounds__(256) void k_aggpk() {
    int gtid = blockIdx.x * blockDim.x + threadIdx.x;
    int n = gtid >> 4;          // node = one 16-lane group
    int q = gtid & 15;          // lane within group: cols [8q, 8q+8)
    if (n >= NN) return;
    int s0 = d_rowstart[n], s1 = d_rowstart[n + 1];
    const uint4* __restrict__ hf4 = (const uint4*)d_hf;
    const int* __restrict__ cs = d_csrc;

    float f0 = 0.f, f1 = 0.f, f2 = 0.f, f3 = 0.f;
    float f4 = 0.f, f5 = 0.f, f6 = 0.f, f7 = 0.f;

    int e = s0;
    #pragma unroll 1
    for (; e + 2 <= s1; e += 2) {
        int i0 = cs[e + 0];
        int i1 = cs[e + 1];
        uint4 a = hf4[i0 * 16 + q];
        uint4 b = hf4[i1 * 16 + q];
        float2 p;
        p = __half22float2(*(__half2*)&a.x); f0 += p.x; f1 += p.y;
        p = __half22float2(*(__half2*)&a.y); f2 += p.x; f3 += p.y;
        p = __half22float2(*(__half2*)&a.z); f4 += p.x; f5 += p.y;
        p = __half22float2(*(__half2*)&a.w); f6 += p.x; f7 += p.y;
        p = __half22float2(*(__half2*)&b.x); f0 += p.x; f1 += p.y;
        p = __half22float2(*(__half2*)&b.y); f2 += p.x; f3 += p.y;
        p = __half22float2(*(__half2*)&b.z); f4 += p.x; f5 += p.y;
        p = __half22float2(*(__half2*)&b.w); f6 += p.x; f7 += p.y;
    }
    if (e < s1) {
        int i0 = cs[e];
        uint4 a = hf4[i0 * 16 + q];
        float2 p;
        p = __half22float2(*(__half2*)&a.x); f0 += p.x; f1 += p.y;
        p = __half22float2(*(__half2*)&a.y); f2 += p.x; f3 += p.y;
        p = __half22float2(*(__half2*)&a.z); f4 += p.x; f5 += p.y;
        p = __half22float2(*(__half2*)&a.w); f6 += p.x; f7 += p.y;
    }
    float inv = d_dinv[n];
    f0 *= inv; f1 *= inv; f2 *= inv; f3 *= inv;
    f4 *= inv; f5 *= inv; f6 *= inv; f7 *= inv;

    uint4 o0, o1;
    o0.x = packhilo(f0, f1, o0.y);
    o0.z = packhilo(f2, f3, o0.w);
    o1.x = packhilo(f4, f5, o1.y);
    o1.z = packhilo(f6, f7, o1.w);
    uint4* Ap4 = (uint4*)d_Apk;
    __stcs(&Ap4[n * 32 + 2 * q + 0], o0);   // streaming: don't pollute L2
    __stcs(&Ap4[n * 32 + 2 * q + 1], o1);
}

// tensor-core GEMM + fused epilogue: h = relu(A@Wc + edge terms + bias + h)
__global__ __launch_bounds__(256) void k_gemm(int l) {
    extern __shared__ uint4 sB[];   // 4096 uint4 = 64KB
    int t = threadIdx.x;
    int warp = t >> 5;
    int lane = t & 31;
    int g = lane >> 2, tig = lane & 3;

    const uint4* Wp = d_Wpk + l * 4096;
    #pragma unroll
    for (int i = t; i < 4096; i += 256) sB[i] = Wp[i];
    __syncthreads();

    int m0 = blockIdx.x * 128 + warp * 16;
    int r0 = m0 + g;
    int r1 = r0 + 8;

    float acc[16][4];
    #pragma unroll
    for (int nf = 0; nf < 16; nf++)
        #pragma unroll
        for (int q = 0; q < 4; q++) acc[nf][q] = 0.f;

    const uint2* Ap = d_Apk;
    for (int ks = 0; ks < 8; ks++) {
        uint2 q0 = __ldcs(&Ap[r0 * 64 + ks * 8 + tig]);        // streaming reads
        uint2 q1 = __ldcs(&Ap[r1 * 64 + ks * 8 + tig]);
        uint2 q2 = __ldcs(&Ap[r0 * 64 + ks * 8 + 4 + tig]);
        uint2 q3 = __ldcs(&Ap[r1 * 64 + ks * 8 + 4 + tig]);
        const uint4* sBk = sB + ks * 512;
        #pragma unroll
        for (int nf = 0; nf < 16; nf++) {
            uint4 bp = sBk[nf * 32 + lane];
            mma16816(acc[nf], q0.x, q1.x, q2.x, q3.x, bp.x, bp.y);
            mma16816(acc[nf], q0.y, q1.y, q2.y, q3.y, bp.x, bp.y);
            mma16816(acc[nf], q0.x, q1.x, q2.x, q3.x, bp.z, bp.w);
        }
    }

    int slot = l + 1;
    float s00 = d_Shat[r0 * 3 + 0], s01 = d_Shat[r0 * 3 + 1], s02 = d_Shat[r0 * 3 + 2];
    float s10 = d_Shat[r1 * 3 + 0], s11 = d_Shat[r1 * 3 + 1], s12 = d_Shat[r1 * 3 + 2];
    const float* bcv = d_bc + slot * HH;
    const float* e0v = d_Wec + slot * 3 * HH;
    const float* e1v = e0v + HH;
    const float* e2v = e1v + HH;

    #pragma unroll
    for (int nf = 0; nf < 16; nf++) {
        int col = nf * 8 + tig * 2;
        float2 bb = *(const float2*)&bcv[col];
        float2 w0 = *(const float2*)&e0v[col];
        float2 w1 = *(const float2*)&e1v[col];
        float2 w2 = *(const float2*)&e2v[col];
        if (r0 < NN) {
            float2 res = __ldcs((const float2*)&d_h[r0 * HH + col]);   // streaming
            float o0 = fmaxf(acc[nf][0] + bb.x + s00 * w0.x + s01 * w1.x + s02 * w2.x + res.x, 0.f);
            float o1 = fmaxf(acc[nf][1] + bb.y + s00 * w0.y + s01 * w1.y + s02 * w2.y + res.y, 0.f);
            __stcs((float2*)&d_h[r0 * HH + col], make_float2(o0, o1)); // streaming
            *(__half2*)&d_hf[r0 * HH + col] = __floats2half2_rn(o0, o1); // hot: default policy
        }
        if (r1 < NN) {
            float2 res = __ldcs((const float2*)&d_h[r1 * HH + col]);
            float o0 = fmaxf(acc[nf][2] + bb.x + s10 * w0.x + s11 * w1.x + s12 * w2.x + res.x, 0.f);
            float o1 = fmaxf(acc[nf][3] + bb.y + s10 * w0.y + s11 * w1.y + s12 * w2.y + res.y, 0.f);
            __stcs((float2*)&d_h[r1 * HH + col], make_float2(o0, o1));
            *(__half2*)&d_hf[r1 * HH + col] = __floats2half2_rn(o0, o1);
        }
    }
}

// ---------------- fused pooling + head ----------------
__global__ __launch_bounds__(256) void k_pool_head(
        const int* __restrict__ batch,
        const float* __restrict__ W1, const float* __restrict__ b1,
        const float* __restrict__ g1, const float* __restrict__ bt1,
        const float* __restrict__ m1, const float* __restrict__ v1,
        const float* __restrict__ W2, const float* __restrict__ b2,
        float* __restrict__ out) {
    __shared__ int sOff[2];
    __shared__ float sin_[2 * HH];
    __shared__ float sz[HH];
    __shared__ float so[OUTD];
    __shared__ float sred[OUTD];
    int gph = blockIdx.x;
    int t = threadIdx.x;
    if (t < 2) {
        int target = gph + t;
        int lo = 0, hi = NN;
        while (lo < hi) {
            int mid = (lo + hi) >> 1;
            if (batch[mid] < target) lo = mid + 1; else hi = mid;
        }
        sOff[t] = lo;
    }
    __syncthreads();
    int s = sOff[0], e = sOff[1];
    if (t < HH) {
        float sum = 0.f, mx = 0.f;
        for (int n = s; n < e; n++) {
            float v = __ldcs(&d_h[n * HH + t]);
            sum += v;
            mx = fmaxf(mx, v);
        }
        float cnt = fmaxf((float)(e - s), 1.0f);
        sin_[t] = sum / cnt;
        sin_[HH + t] = mx;
    }
    __syncthreads();
    if (t < HH) {
        float acc = b1[t];
        #pragma unroll 8
        for (int k = 0; k < 2 * HH; k++) acc += sin_[k] * W1[k * HH + t];
        float sc = g1[t] * rsqrtf(v1[t] + BNEPS);
        sz[t] = fmaxf((acc - m1[t]) * sc + bt1[t], 0.f);
    }
    __syncthreads();
    float o = b2[t];
    #pragma unroll 8
    for (int jj = 0; jj < HH; jj++) o += sz[jj] * W2[jj * OUTD + t];
    so[t] = o;
    sred[t] = o * o;
    __syncthreads();
    for (int st = 128; st > 0; st >>= 1) {
        if (t < st) sred[t] += sred[t + st];
        __syncthreads();
    }
    float scale = 1.0f / fmaxf(sqrtf(sred[0]), 1e-12f);
    out[gph * OUTD + t] = so[t] * scale;
}

// ---------------- launch ----------------
extern "C" void kernel_launch(void* const* d_in, const int* in_sizes, int n_in,
                              void* d_out, int out_size) {
    const float* x     = (const float*)d_in[0];
    const float* ea    = (const float*)d_in[1];
    const float* We0   = (const float*)d_in[2];
    const float* be0   = (const float*)d_in[3];
    const float* Wn0   = (const float*)d_in[4];
    const float* bno0  = (const float*)d_in[5];
    const float* g0    = (const float*)d_in[6];
    const float* bt0   = (const float*)d_in[7];
    const float* m0    = (const float*)d_in[8];
    const float* v0    = (const float*)d_in[9];
    const float* Wr0   = (const float*)d_in[10];
    const float* br0   = (const float*)d_in[11];
    const float* We_s  = (const float*)d_in[12];
    const float* be_s  = (const float*)d_in[13];
    const float* Wn_s  = (const float*)d_in[14];
    const float* bno_s = (const float*)d_in[15];
    const float* g_s   = (const float*)d_in[16];
    const float* bt_s  = (const float*)d_in[17];
    const float* m_s   = (const float*)d_in[18];
    const float* v_s   = (const float*)d_in[19];
    const float* W1    = (const float*)d_in[20];
    const float* b1    = (const float*)d_in[21];
    const float* g1    = (const float*)d_in[22];
    const float* bt1   = (const float*)d_in[23];
    const float* m1    = (const float*)d_in[24];
    const float* v1    = (const float*)d_in[25];
    const float* W2    = (const float*)d_in[26];
    const float* b2    = (const float*)d_in[27];
    const int* ei      = (const int*)d_in[28];
    const int* batch   = (const int*)d_in[29];
    const int* src = ei;
    const int* dst = ei + EE;

    cudaFuncSetAttribute(k_gemm, cudaFuncAttributeMaxDynamicSharedMemorySize, 65536);

    k_zero<<<(2 * NN + 255) / 256, 256>>>();
    k_deg_se<<<(EE + 255) / 256, 256>>>(dst, ea);
    k_bsum<<<NB, 256>>>();
    k_rowstart_shat<<<NB, 256>>>();
    k_fill<<<(EE + 255) / 256, 256>>>(src, dst);
    k_prep<<<(LL * 4096 + 4 * HH + 8 * 3 * HH + 8 * HH + 255) / 256, 256>>>(
        We0, Wn0, g0, v0, be0, bno0, m0, bt0,
        We_s, Wn_s, g_s, v_s, be_s, bno_s, m_s, bt_s);

    k_agg4<<<(NN + 255) / 256, 256>>>(x);
    k_update0<<<(NN * 128 + 255) / 256, 256>>>(x, Wr0, br0);

    for (int l = 0; l < LL; l++) {
        k_aggpk<<<(NN * 16 + 255) / 256, 256>>>();
        k_gemm<<<NPAD / 128, 256, 65536>>>(l);
    }

    k_pool_head<<<GG, 256>>>(batch, W1, b1, g1, bt1, m1, v1, W2, b2, (float*)d_out);
}

// round 8
// speedup vs baseline: 1.0726x; 1.0726x over previous
#include <cuda_runtime.h>
#include <cuda_fp16.h>
#include <math.h>

#define NN 50000
#define NPAD 50048
#define EE 600000
#define GG 512
#define HH 128
#define OUTD 256
#define LL 7
#define BNEPS 1e-5f
#define NB 49   // scan blocks of 1024

// ---------------- scratch (device globals; no allocs) ----------------
__device__ float  d_h[NPAD * HH];     // fp32 h
__device__ uint2  d_Apk[NPAD * 64];   // packed A fragments {hi2, lo2}
__device__ int    d_degI[NN];
__device__ int    d_rowstart[NN + 1];
__device__ int    d_cursor[NN];
__device__ int    d_csrc[EE];
__device__ float  d_Se[NN * 2];
__device__ float  d_Shat[NPAD * 3];   // pad region stays 0 (static zero-init)
__device__ float  d_dinv[NN];
__device__ int    d_sflag[NB];        // lookback-scan state
__device__ int    d_sagg[NB];
__device__ int    d_sinc[NB];
__device__ uint4  d_Wpk[LL * 4096];   // packed W fragments {bhi0,bhi1,blo0,blo1}
__device__ float  d_Wc0[4 * HH];
__device__ float  d_Wec[8 * 3 * HH];
__device__ float  d_bc[8 * HH];

static __device__ __forceinline__ unsigned packh2(__half a, __half b) {
    __half2 h = __halves2half2(a, b);
    return *(unsigned*)&h;
}

static __device__ __forceinline__ unsigned packhilo(float x, float y, unsigned& lo) {
    __half hx = __float2half_rn(x), hy = __float2half_rn(y);
    __half lx = __float2half_rn(x - __half2float(hx));
    __half ly = __float2half_rn(y - __half2float(hy));
    lo = packh2(lx, ly);
    return packh2(hx, hy);
}

static __device__ __forceinline__ void mma16816(float* c,
        unsigned a0, unsigned a1, unsigned a2, unsigned a3,
        unsigned b0, unsigned b1) {
    asm volatile(
        "mma.sync.aligned.m16n8k16.row.col.f32.f16.f16.f32 "
        "{%0,%1,%2,%3}, {%4,%5,%6,%7}, {%8,%9}, {%0,%1,%2,%3};\n"
        : "+f"(c[0]), "+f"(c[1]), "+f"(c[2]), "+f"(c[3])
        : "r"(a0), "r"(a1), "r"(a2), "r"(a3), "r"(b0), "r"(b1));
}

// ---------------- launch 1: zeroing + all weight folding ----------------
__global__ void k_prep_zero(
    const float* __restrict__ We0, const float* __restrict__ Wn0,
    const float* __restrict__ g0,  const float* __restrict__ v0,
    const float* __restrict__ be0, const float* __restrict__ bno0,
    const float* __restrict__ m0,  const float* __restrict__ bt0,
    const float* __restrict__ We_s, const float* __restrict__ Wn_s,
    const float* __restrict__ g_s,  const float* __restrict__ v_s,
    const float* __restrict__ be_s, const float* __restrict__ bno_s,
    const float* __restrict__ m_s,  const float* __restrict__ bt_s) {
    int idx = blockIdx.x * blockDim.x + threadIdx.x;
    if (idx < NN) { d_degI[idx] = 0; d_cursor[idx] = 0; }
    if (idx < 2 * NN) d_Se[idx] = 0.f;
    if (idx < NB) d_sflag[idx] = 0;

    if (idx < LL * 4096) {
        int l = idx / 4096, e = idx % 4096;
        int ks = e / 512;
        int rem = e % 512;
        int nf = rem / 32, lane = rem % 32;
        int g = lane >> 2, tig = lane & 3;
        int n = nf * 8 + g;
        int k0 = ks * 16 + tig * 2;
        const float* We = We_s + l * (HH + 2) * HH;
        const float* Wn = Wn_s + l * HH * HH;
        float s = g_s[l * HH + n] * rsqrtf(v_s[l * HH + n] + BNEPS);
        float w00 = 0.f, w01 = 0.f, w10 = 0.f, w11 = 0.f;
        #pragma unroll 4
        for (int m = 0; m < HH; m++) {
            float wn = Wn[m * HH + n];
            w00 += We[(k0 + 0) * HH + m] * wn;
            w01 += We[(k0 + 1) * HH + m] * wn;
            w10 += We[(k0 + 8) * HH + m] * wn;
            w11 += We[(k0 + 9) * HH + m] * wn;
        }
        w00 *= s; w01 *= s; w10 *= s; w11 *= s;
        uint4 o;
        o.x = packhilo(w00, w01, o.z);
        o.y = packhilo(w10, w11, o.w);
        d_Wpk[idx] = o;
        return;
    }
    int q = idx - LL * 4096;
    if (q < 4 * HH) {
        int k = q / HH, j = q % HH;
        float s = g0[j] * rsqrtf(v0[j] + BNEPS);
        float acc = 0.f;
        for (int m = 0; m < HH; m++) acc += We0[k * HH + m] * Wn0[m * HH + j];
        d_Wc0[q] = acc * s;
    } else if (q < 4 * HH + 8 * 3 * HH) {
        int t = q - 4 * HH;
        int l = t / (3 * HH);
        int r = (t / HH) % 3;
        int j = t % HH;
        const float* Wn; const float* row; float s;
        if (l == 0) {
            Wn = Wn0;
            s = g0[j] * rsqrtf(v0[j] + BNEPS);
            row = (r < 2) ? (We0 + (4 + r) * HH) : be0;
        } else {
            int lw = l - 1;
            Wn = Wn_s + lw * HH * HH;
            s = g_s[lw * HH + j] * rsqrtf(v_s[lw * HH + j] + BNEPS);
            row = (r < 2) ? (We_s + lw * (HH + 2) * HH + (HH + r) * HH) : (be_s + lw * HH);
        }
        float acc = 0.f;
        for (int m = 0; m < HH; m++) acc += row[m] * Wn[m * HH + j];
        d_Wec[l * 3 * HH + r * HH + j] = acc * s;
    } else if (q < 4 * HH + 8 * 3 * HH + 8 * HH) {
        int t = q - 4 * HH - 8 * 3 * HH;
        int l = t / HH, j = t % HH;
        float s, bn, mm, bt;
        if (l == 0) { s = g0[j] * rsqrtf(v0[j] + BNEPS); bn = bno0[j]; mm = m0[j]; bt = bt0[j]; }
        else {
            int lw = l - 1;
            s = g_s[lw * HH + j] * rsqrtf(v_s[lw * HH + j] + BNEPS);
            bn = bno_s[lw * HH + j]; mm = m_s[lw * HH + j]; bt = bt_s[lw * HH + j];
        }
        d_bc[l * HH + j] = (bn - mm) * s + bt;
    }
}

// ---------------- launch 2: degree + edge-feature sums ----------------
__global__ void k_deg_se(const int* __restrict__ dst, const float* __restrict__ ea) {
    int e = blockIdx.x * blockDim.x + threadIdx.x;
    if (e >= EE) return;
    int d = dst[e];
    atomicAdd(&d_degI[d], 1);
    atomicAdd(&d_Se[d * 2 + 0], ea[e * 2 + 0]);
    atomicAdd(&d_Se[d * 2 + 1], ea[e * 2 + 1]);
}

// ---------------- launch 3: single-pass decoupled-lookback scan + shat ----------------
__global__ __launch_bounds__(256) void k_scan_shat() {
    __shared__ int wsum[8];
    __shared__ int s_excl;
    int b = blockIdx.x, t = threadIdx.x;
    int base_idx = b * 1024 + t * 4;
    int v[4];
    #pragma unroll
    for (int i = 0; i < 4; i++) { int idx = base_idx + i; v[i] = (idx < NN) ? d_degI[idx] : 0; }
    int tsum = v[0] + v[1] + v[2] + v[3];
    int lane = t & 31, wid = t >> 5;
    int s = tsum;
    for (int o = 1; o < 32; o <<= 1) { int u = __shfl_up_sync(~0u, s, o); if (lane >= o) s += u; }
    if (lane == 31) wsum[wid] = s;
    __syncthreads();
    if (t == 0) {
        int c = 0;
        for (int w = 0; w < 8; w++) { int x = wsum[w]; wsum[w] = c; c += x; }
        // publish aggregate
        *(volatile int*)&d_sagg[b] = c;
        __threadfence();
        atomicExch(&d_sflag[b], 1);
        // lookback
        int run = 0;
        for (int i = b - 1; i >= 0; ) {
            int f;
            do { f = atomicAdd(&d_sflag[i], 0); } while (f == 0);
            if (f == 2) { run += *(volatile int*)&d_sinc[i]; break; }
            run += *(volatile int*)&d_sagg[i];
            i--;
        }
        *(volatile int*)&d_sinc[b] = run + c;
        __threadfence();
        atomicExch(&d_sflag[b], 2);
        s_excl = run;
    }
    __syncthreads();
    int run = s_excl + wsum[wid] + (s - tsum);
    #pragma unroll
    for (int i = 0; i < 4; i++) {
        int idx = base_idx + i;
        if (idx < NN) {
            d_rowstart[idx] = run;
            int dg = v[i];
            float inv = 1.0f / (float)max(dg, 1);
            d_dinv[idx] = inv;
            d_Shat[idx * 3 + 0] = d_Se[idx * 2 + 0] * inv;
            d_Shat[idx * 3 + 1] = d_Se[idx * 2 + 1] * inv;
            d_Shat[idx * 3 + 2] = (dg > 0) ? 1.0f : 0.0f;
        }
        run += v[i];
    }
    if (b == 0 && t == 0) d_rowstart[NN] = EE;
}

// ---------------- launch 4: CSR fill ----------------
__global__ void k_fill(const int* __restrict__ src, const int* __restrict__ dst) {
    int e = blockIdx.x * blockDim.x + threadIdx.x;
    if (e >= EE) return;
    int d = dst[e];
    int pos = d_rowstart[d] + atomicAdd(&d_cursor[d], 1);
    d_csrc[pos] = src[e];
}

// ---------------- launch 5: fused layer 0 (agg4 + update) ----------------
__global__ __launch_bounds__(128) void k_layer0(const float* __restrict__ x,
        const float* __restrict__ Wr0, const float* __restrict__ br0) {
    __shared__ float sA[4][4];
    int b = blockIdx.x;
    int t = threadIdx.x;
    int wid = t >> 5, lane = t & 31;
    int n = b * 4 + wid;
    float4 acc = make_float4(0.f, 0.f, 0.f, 0.f);
    const float4* x4 = (const float4*)x;
    if (n < NN) {
        int s0 = d_rowstart[n], s1 = d_rowstart[n + 1];
        for (int e = s0 + lane; e < s1; e += 32) {
            float4 xv = x4[d_csrc[e]];
            acc.x += xv.x; acc.y += xv.y; acc.z += xv.z; acc.w += xv.w;
        }
    }
    #pragma unroll
    for (int o = 16; o > 0; o >>= 1) {
        acc.x += __shfl_down_sync(~0u, acc.x, o);
        acc.y += __shfl_down_sync(~0u, acc.y, o);
        acc.z += __shfl_down_sync(~0u, acc.z, o);
        acc.w += __shfl_down_sync(~0u, acc.w, o);
    }
    if (lane == 0 && n < NN) {
        float inv = d_dinv[n];
        sA[wid][0] = acc.x * inv; sA[wid][1] = acc.y * inv;
        sA[wid][2] = acc.z * inv; sA[wid][3] = acc.w * inv;
    }
    __syncthreads();
    int j = t;
    #pragma unroll
    for (int r = 0; r < 4; r++) {
        int node = b * 4 + r;
        if (node >= NN) break;
        float4 xr = x4[node];
        float s0 = d_Shat[node * 3 + 0], s1 = d_Shat[node * 3 + 1], s2 = d_Shat[node * 3 + 2];
        float v = d_bc[j]
            + sA[r][0] * d_Wc0[0 * HH + j] + sA[r][1] * d_Wc0[1 * HH + j]
            + sA[r][2] * d_Wc0[2 * HH + j] + sA[r][3] * d_Wc0[3 * HH + j]
            + s0 * d_Wec[0 * HH + j] + s1 * d_Wec[1 * HH + j] + s2 * d_Wec[2 * HH + j];
        float res = br0[j]
            + xr.x * Wr0[0 * HH + j] + xr.y * Wr0[1 * HH + j]
            + xr.z * Wr0[2 * HH + j] + xr.w * Wr0[3 * HH + j];
        d_h[node * HH + j] = fmaxf(v + res, 0.f);
    }
}

// ---------------- layers 1..7 ----------------
// aggregate h (fp32) -> packed A (hi/lo fp16), one warp per node, 4-way batching
__global__ __launch_bounds__(256) void k_aggpk() {
    int gtid = blockIdx.x * blockDim.x + threadIdx.x;
    int n = gtid >> 5;
    int lane = gtid & 31;
    if (n >= NN) return;
    int s0 = d_rowstart[n], s1 = d_rowstart[n + 1];
    const float4* __restrict__ h4 = (const float4*)d_h;
    const int* __restrict__ cs = d_csrc;
    float4 acc0 = make_float4(0.f, 0.f, 0.f, 0.f);
    float4 acc1 = make_float4(0.f, 0.f, 0.f, 0.f);
    int e = s0;
    #pragma unroll 1
    for (; e + 4 <= s1; e += 4) {
        int i0 = cs[e + 0];
        int i1 = cs[e + 1];
        int i2 = cs[e + 2];
        int i3 = cs[e + 3];
        float4 a = h4[i0 * 32 + lane];
        float4 b = h4[i1 * 32 + lane];
        float4 c = h4[i2 * 32 + lane];
        float4 d = h4[i3 * 32 + lane];
        acc0.x += a.x + b.x; acc0.y += a.y + b.y; acc0.z += a.z + b.z; acc0.w += a.w + b.w;
        acc1.x += c.x + d.x; acc1.y += c.y + d.y; acc1.z += c.z + d.z; acc1.w += c.w + d.w;
    }
    #pragma unroll 1
    for (; e < s1; e++) {
        int s = cs[e];
        float4 v = h4[s * 32 + lane];
        acc0.x += v.x; acc0.y += v.y; acc0.z += v.z; acc0.w += v.w;
    }
    float inv = d_dinv[n];
    float ax = (acc0.x + acc1.x) * inv;
    float ay = (acc0.y + acc1.y) * inv;
    float az = (acc0.z + acc1.z) * inv;
    float aw = (acc0.w + acc1.w) * inv;
    uint4 o;
    o.x = packhilo(ax, ay, o.y);
    o.z = packhilo(az, aw, o.w);
    ((uint4*)d_Apk)[n * 32 + lane] = o;
}

// tensor-core GEMM + fused epilogue: h = relu(A@Wc + edge terms + bias + h)
__global__ __launch_bounds__(256) void k_gemm(int l) {
    extern __shared__ uint4 sB[];   // 4096 uint4 = 64KB
    int t = threadIdx.x;
    int warp = t >> 5;
    int lane = t & 31;
    int g = lane >> 2, tig = lane & 3;

    const uint4* Wp = d_Wpk + l * 4096;
    #pragma unroll
    for (int i = t; i < 4096; i += 256) sB[i] = Wp[i];
    __syncthreads();

    int m0 = blockIdx.x * 128 + warp * 16;
    int r0 = m0 + g;
    int r1 = r0 + 8;

    float acc[16][4];
    #pragma unroll
    for (int nf = 0; nf < 16; nf++)
        #pragma unroll
        for (int q = 0; q < 4; q++) acc[nf][q] = 0.f;

    const uint2* Ap = d_Apk;
    for (int ks = 0; ks < 8; ks++) {
        uint2 q0 = Ap[r0 * 64 + ks * 8 + tig];
        uint2 q1 = Ap[r1 * 64 + ks * 8 + tig];
        uint2 q2 = Ap[r0 * 64 + ks * 8 + 4 + tig];
        uint2 q3 = Ap[r1 * 64 + ks * 8 + 4 + tig];
        const uint4* sBk = sB + ks * 512;
        #pragma unroll
        for (int nf = 0; nf < 16; nf++) {
            uint4 bp = sBk[nf * 32 + lane];
            mma16816(acc[nf], q0.x, q1.x, q2.x, q3.x, bp.x, bp.y);
            mma16816(acc[nf], q0.y, q1.y, q2.y, q3.y, bp.x, bp.y);
            mma16816(acc[nf], q0.x, q1.x, q2.x, q3.x, bp.z, bp.w);
        }
    }

    int slot = l + 1;
    float s00 = d_Shat[r0 * 3 + 0], s01 = d_Shat[r0 * 3 + 1], s02 = d_Shat[r0 * 3 + 2];
    float s10 = d_Shat[r1 * 3 + 0], s11 = d_Shat[r1 * 3 + 1], s12 = d_Shat[r1 * 3 + 2];
    const float* bcv = d_bc + slot * HH;
    const float* e0v = d_Wec + slot * 3 * HH;
    const float* e1v = e0v + HH;
    const float* e2v = e1v + HH;

    #pragma unroll
    for (int nf = 0; nf < 16; nf++) {
        int col = nf * 8 + tig * 2;
        float2 bb = *(const float2*)&bcv[col];
        float2 w0 = *(const float2*)&e0v[col];
        float2 w1 = *(const float2*)&e1v[col];
        float2 w2 = *(const float2*)&e2v[col];
        if (r0 < NN) {
            float2 res = *(const float2*)&d_h[r0 * HH + col];
            float o0 = acc[nf][0] + bb.x + s00 * w0.x + s01 * w1.x + s02 * w2.x + res.x;
            float o1 = acc[nf][1] + bb.y + s00 * w0.y + s01 * w1.y + s02 * w2.y + res.y;
            *(float2*)&d_h[r0 * HH + col] = make_float2(fmaxf(o0, 0.f), fmaxf(o1, 0.f));
        }
        if (r1 < NN) {
            float2 res = *(const float2*)&d_h[r1 * HH + col];
            float o0 = acc[nf][2] + bb.x + s10 * w0.x + s11 * w1.x + s12 * w2.x + res.x;
            float o1 = acc[nf][3] + bb.y + s10 * w0.y + s11 * w1.y + s12 * w2.y + res.y;
            *(float2*)&d_h[r1 * HH + col] = make_float2(fmaxf(o0, 0.f), fmaxf(o1, 0.f));
        }
    }
}

// ---------------- fused pooling + head ----------------
__global__ __launch_bounds__(256) void k_pool_head(
        const int* __restrict__ batch,
        const float* __restrict__ W1, const float* __restrict__ b1,
        const float* __restrict__ g1, const float* __restrict__ bt1,
        const float* __restrict__ m1, const float* __restrict__ v1,
        const float* __restrict__ W2, const float* __restrict__ b2,
        float* __restrict__ out) {
    __shared__ int sOff[2];
    __shared__ float sin_[2 * HH];
    __shared__ float sz[HH];
    __shared__ float so[OUTD];
    __shared__ float sred[OUTD];
    int gph = blockIdx.x;
    int t = threadIdx.x;
    if (t < 2) {
        int target = gph + t;
        int lo = 0, hi = NN;
        while (lo < hi) {
            int mid = (lo + hi) >> 1;
            if (batch[mid] < target) lo = mid + 1; else hi = mid;
        }
        sOff[t] = lo;
    }
    __syncthreads();
    int s = sOff[0], e = sOff[1];
    if (t < HH) {
        float sum = 0.f, mx = 0.f;
        for (int n = s; n < e; n++) {
            float v = d_h[n * HH + t];
            sum += v;
            mx = fmaxf(mx, v);
        }
        float cnt = fmaxf((float)(e - s), 1.0f);
        sin_[t] = sum / cnt;
        sin_[HH + t] = mx;
    }
    __syncthreads();
    if (t < HH) {
        float acc = b1[t];
        #pragma unroll 8
        for (int k = 0; k < 2 * HH; k++) acc += sin_[k] * W1[k * HH + t];
        float sc = g1[t] * rsqrtf(v1[t] + BNEPS);
        sz[t] = fmaxf((acc - m1[t]) * sc + bt1[t], 0.f);
    }
    __syncthreads();
    float o = b2[t];
    #pragma unroll 8
    for (int jj = 0; jj < HH; jj++) o += sz[jj] * W2[jj * OUTD + t];
    so[t] = o;
    sred[t] = o * o;
    __syncthreads();
    for (int st = 128; st > 0; st >>= 1) {
        if (t < st) sred[t] += sred[t + st];
        __syncthreads();
    }
    float scale = 1.0f / fmaxf(sqrtf(sred[0]), 1e-12f);
    out[gph * OUTD + t] = so[t] * scale;
}

// ---------------- launch ----------------
extern "C" void kernel_launch(void* const* d_in, const int* in_sizes, int n_in,
                              void* d_out, int out_size) {
    const float* x     = (const float*)d_in[0];
    const float* ea    = (const float*)d_in[1];
    const float* We0   = (const float*)d_in[2];
    const float* be0   = (const float*)d_in[3];
    const float* Wn0   = (const float*)d_in[4];
    const float* bno0  = (const float*)d_in[5];
    const float* g0    = (const float*)d_in[6];
    const float* bt0   = (const float*)d_in[7];
    const float* m0    = (const float*)d_in[8];
    const float* v0    = (const float*)d_in[9];
    const float* Wr0   = (const float*)d_in[10];
    const float* br0   = (const float*)d_in[11];
    const float* We_s  = (const float*)d_in[12];
    const float* be_s  = (const float*)d_in[13];
    const float* Wn_s  = (const float*)d_in[14];
    const float* bno_s = (const float*)d_in[15];
    const float* g_s   = (const float*)d_in[16];
    const float* bt_s  = (const float*)d_in[17];
    const float* m_s   = (const float*)d_in[18];
    const float* v_s   = (const float*)d_in[19];
    const float* W1    = (const float*)d_in[20];
    const float* b1    = (const float*)d_in[21];
    const float* g1    = (const float*)d_in[22];
    const float* bt1   = (const float*)d_in[23];
    const float* m1    = (const float*)d_in[24];
    const float* v1    = (const float*)d_in[25];
    const float* W2    = (const float*)d_in[26];
    const float* b2    = (const float*)d_in[27];
    const int* ei      = (const int*)d_in[28];
    const int* batch   = (const int*)d_in[29];
    const int* src = ei;
    const int* dst = ei + EE;

    cudaFuncSetAttribute(k_gemm, cudaFuncAttributeMaxDynamicSharedMemorySize, 65536);

    // launches 1-5: preprocessing (6th launch overall = first k_aggpk -> ncu profiles it)
    k_prep_zero<<<(2 * NN + 255) / 256, 256>>>(
        We0, Wn0, g0, v0, be0, bno0, m0, bt0,
        We_s, Wn_s, g_s, v_s, be_s, bno_s, m_s, bt_s);
    k_deg_se<<<(EE + 255) / 256, 256>>>(dst, ea);
    k_scan_shat<<<NB, 256>>>();
    k_fill<<<(EE + 255) / 256, 256>>>(src, dst);
    k_layer0<<<(NN + 3) / 4, 128>>>(x, Wr0, br0);

    for (int l = 0; l < LL; l++) {
        k_aggpk<<<(NN * 32 + 255) / 256, 256>>>();
        k_gemm<<<NPAD / 128, 256, 65536>>>(l);
    }

    k_pool_head<<<GG, 256>>>(batch, W1, b1, g1, bt1, m1, v1, W2, b2, (float*)d_out);
}